// round 15
// baseline (speedup 1.0000x reference)
#include <cuda_runtime.h>
#include <cuda_bf16.h>
#include <cstdint>

#define B_ 256
#define T_ 256
#define F_ 512
#define H_ 1024
#define A_ 1000

// recurrence: 128 blocks = 2 row-groups(128) x 8 col-groups(128) x 8 k-splits(128)
#define NBLK 128
#define RTHREADS 512
#define RROWS 128
#define RCOLS 128
#define RK    128
#define NSPLIT 8
#define MPI   136   // smem pitch (floats): conflict-free mma fragment access
#define CK    16    // k per staging chunk
#define NCHK  (RK / CK)   // 8

// ---------------- scratch (static device globals; no allocation) -------------
__device__ float g_xw[(size_t)B_ * T_ * H_];      // input projection [B][T][H]
__device__ float g_part[2][NSPLIT][B_ * H_];      // double-buffered partials
__device__ float g_hid[B_ * H_];
__device__ float g_logits[B_ * A_];
__device__ int   g_action[B_];
__device__ float g_rowloss[B_];

// grid barrier state (self-cleaning; safe across graph replays)
__device__ unsigned g_cnt = 0;
__device__ volatile unsigned g_gen = 0;

// ---------------- packed fp32x2 FMA helpers (sgemm for logits) ---------------
__device__ __forceinline__ unsigned long long pack2(float lo, float hi) {
    unsigned long long r;
    asm("mov.b64 %0, {%1, %2};" : "=l"(r) : "f"(lo), "f"(hi));
    return r;
}
__device__ __forceinline__ void unpack2(unsigned long long v, float& lo, float& hi) {
    asm("mov.b64 {%0, %1}, %2;" : "=f"(lo), "=f"(hi) : "l"(v));
}
__device__ __forceinline__ void ffma2(unsigned long long& d, unsigned long long a,
                                      unsigned long long b) {
    asm("fma.rn.f32x2 %0, %1, %2, %0;" : "+l"(d) : "l"(a), "l"(b));
}

// ---------------- tf32 split + mma.sync helpers ------------------------------
__device__ __forceinline__ void tf32_split(float x, uint32_t& u0, uint32_t& u1) {
    asm("cvt.rna.tf32.f32 %0, %1;" : "=r"(u0) : "f"(x));
    float r = x - __uint_as_float(u0);
    asm("cvt.rna.tf32.f32 %0, %1;" : "=r"(u1) : "f"(r));
}
__device__ __forceinline__ void mma_tf32(float c[4], const uint32_t a[4],
                                         const uint32_t b[2]) {
    asm volatile(
        "mma.sync.aligned.m16n8k8.row.col.f32.tf32.tf32.f32 "
        "{%0,%1,%2,%3}, {%4,%5,%6,%7}, {%8,%9}, {%0,%1,%2,%3};"
        : "+f"(c[0]), "+f"(c[1]), "+f"(c[2]), "+f"(c[3])
        : "r"(a[0]), "r"(a[1]), "r"(a[2]), "r"(a[3]), "r"(b[0]), "r"(b[1]));
}

// ---------------- phase-A 3xTF32 tensor GEMM (unchanged from R12) ------------
#define PITA 136
#define GA_CH 16
#define GA_NCH (F_ / GA_CH)        // 32 chunks
#define GA_TILE (GA_CH * PITA)

__global__ void __launch_bounds__(256, 1)
gemm_a_mma(const float* __restrict__ Ag, const float* __restrict__ Bg,
           const float* __restrict__ bias, float* __restrict__ C)
{
    extern __shared__ __align__(16) float sm[];
    float* sA0 = sm;
    float* sA1 = sm + 2 * GA_TILE;
    float* sB0 = sm + 4 * GA_TILE;
    float* sB1 = sm + 6 * GA_TILE;

    const int tid  = threadIdx.x;
    const int lane = tid & 31;
    const int w    = tid >> 5;
    const int wm   = w >> 2;
    const int wn   = w & 3;
    const int bm   = blockIdx.y * 128;
    const int bn   = blockIdx.x * 128;
    const int g    = lane >> 2;
    const int tg   = lane & 3;

    const int a_k4  = tid >> 7;
    const int a_row = tid & 127;
    const int b_k   = tid >> 5;
    const int b_n4  = lane;

    float4 aReg[2], bReg[2];
    auto loadG = [&](int k0) {
#pragma unroll
        for (int j = 0; j < 2; ++j) {
            aReg[j] = __ldg((const float4*)(Ag + (size_t)(bm + a_row) * F_ +
                                            k0 + (a_k4 + 2 * j) * 4));
            bReg[j] = __ldg((const float4*)(Bg + (size_t)(k0 + b_k + 8 * j) * H_ +
                                            bn + b_n4 * 4));
        }
    };
    auto storeS = [&](int buf) {
        float* dA0 = sA0 + buf * GA_TILE;
        float* dA1 = sA1 + buf * GA_TILE;
        float* dB0 = sB0 + buf * GA_TILE;
        float* dB1 = sB1 + buf * GA_TILE;
#pragma unroll
        for (int j = 0; j < 2; ++j) {
            const int kb = (a_k4 + 2 * j) * 4;
            const float av[4] = {aReg[j].x, aReg[j].y, aReg[j].z, aReg[j].w};
#pragma unroll
            for (int e = 0; e < 4; ++e) {
                uint32_t u0, u1;
                tf32_split(av[e], u0, u1);
                dA0[(kb + e) * PITA + a_row] = __uint_as_float(u0);
                dA1[(kb + e) * PITA + a_row] = __uint_as_float(u1);
            }
            const int kr = b_k + 8 * j;
            const float bv[4] = {bReg[j].x, bReg[j].y, bReg[j].z, bReg[j].w};
            uint4 q0, q1;
            uint32_t* p0 = (uint32_t*)&q0;
            uint32_t* p1 = (uint32_t*)&q1;
#pragma unroll
            for (int e = 0; e < 4; ++e) tf32_split(bv[e], p0[e], p1[e]);
            *(uint4*)(dB0 + kr * PITA + b_n4 * 4) = q0;
            *(uint4*)(dB1 + kr * PITA + b_n4 * 4) = q1;
        }
    };

    float c[4][4][4];
#pragma unroll
    for (int i = 0; i < 4; ++i)
#pragma unroll
        for (int j = 0; j < 4; ++j)
#pragma unroll
            for (int e = 0; e < 4; ++e) c[i][j][e] = 0.0f;

    loadG(0);
    storeS(0);
    __syncthreads();

    for (int kt = 0; kt < GA_NCH; ++kt) {
        const int cur = kt & 1;
        if (kt + 1 < GA_NCH) loadG((kt + 1) * GA_CH);

        const float* cA0 = sA0 + cur * GA_TILE;
        const float* cA1 = sA1 + cur * GA_TILE;
        const float* cB0 = sB0 + cur * GA_TILE;
        const float* cB1 = sB1 + cur * GA_TILE;

#pragma unroll
        for (int s = 0; s < 2; ++s) {
            const int ko = s * 8;
            uint32_t bt0[4][2], bt1[4][2];
#pragma unroll
            for (int in = 0; in < 4; ++in) {
                const int an = wn * 32 + in * 8 + g;
                bt0[in][0] = __float_as_uint(cB0[(ko + tg) * PITA + an]);
                bt0[in][1] = __float_as_uint(cB0[(ko + tg + 4) * PITA + an]);
                bt1[in][0] = __float_as_uint(cB1[(ko + tg) * PITA + an]);
                bt1[in][1] = __float_as_uint(cB1[(ko + tg + 4) * PITA + an]);
            }
#pragma unroll
            for (int im = 0; im < 4; ++im) {
                const int am = wm * 64 + im * 16 + g;
                uint32_t a0[4], a1[4];
                a0[0] = __float_as_uint(cA0[(ko + tg) * PITA + am]);
                a0[1] = __float_as_uint(cA0[(ko + tg) * PITA + am + 8]);
                a0[2] = __float_as_uint(cA0[(ko + tg + 4) * PITA + am]);
                a0[3] = __float_as_uint(cA0[(ko + tg + 4) * PITA + am + 8]);
                a1[0] = __float_as_uint(cA1[(ko + tg) * PITA + am]);
                a1[1] = __float_as_uint(cA1[(ko + tg) * PITA + am + 8]);
                a1[2] = __float_as_uint(cA1[(ko + tg + 4) * PITA + am]);
                a1[3] = __float_as_uint(cA1[(ko + tg + 4) * PITA + am + 8]);
#pragma unroll
                for (int in = 0; in < 4; ++in) {
                    mma_tf32(c[im][in], a0, bt1[in]);
                    mma_tf32(c[im][in], a1, bt0[in]);
                    mma_tf32(c[im][in], a0, bt0[in]);
                }
            }
        }

        if (kt + 1 < GA_NCH) storeS(cur ^ 1);
        __syncthreads();
    }

#pragma unroll
    for (int im = 0; im < 4; ++im) {
        const int r0 = bm + wm * 64 + im * 16 + g;
#pragma unroll
        for (int in = 0; in < 4; ++in) {
            const int n0 = bn + wn * 32 + in * 8 + 2 * tg;
            float2 bv = *(const float2*)&bias[n0];
            float2 o0 = {c[im][in][0] + bv.x, c[im][in][1] + bv.y};
            float2 o1 = {c[im][in][2] + bv.x, c[im][in][3] + bv.y};
            *(float2*)&C[(size_t)r0 * H_ + n0]       = o0;
            *(float2*)&C[(size_t)(r0 + 8) * H_ + n0] = o1;
        }
    }
}

// ---------------- grid-wide barrier ------------------------------------------
__device__ __forceinline__ void grid_sync() {
    __syncthreads();
    if (threadIdx.x == 0) {
        __threadfence();
        unsigned gen = g_gen;
        unsigned old = atomicAdd(&g_cnt, 1u);
        if (old == NBLK - 1) {
            g_cnt = 0;
            __threadfence();
            g_gen = gen + 1;
        } else {
            while (g_gen == gen) { }
            __threadfence();
        }
    }
    __syncthreads();
}

// ---------------- persistent recurrence: fused-reduce 3xTF32 mma -------------
// Block (r,c,q): rows [r*128,+128), cols [c*128,+128), k in [q*128,+128).
// Wh slab pre-split once into 2 tf32 terms, [k][n] pitch-136 (139 KB resident).
// 512 threads, 16 warps in 4x4 grid (32x32 tiles). h is NEVER materialized:
// staging computes h = relu(xw + sum_q part) on the fly from double-buffered
// partials (read buf t&1, write buf (t+1)&1) -> ONE grid barrier per step.
// 8 chunks of 16 k, double-buffered staging; loads for chunk ch+1 prefetched
// into registers during chunk ch's HMMA.

struct RecurSmem {
    float W0[RK * MPI];          // 69632 B (slab term 0)
    float W1s[RK * MPI];         // 69632 B (slab term 1)
    float A0[2 * CK * MPI];      // 17408 B (staging term 0, 2 bufs)
    float A1[2 * CK * MPI];      // 17408 B (term 1)
};                               // total 174080 B

__device__ __forceinline__ void split_slab(
    const float* __restrict__ Wg, float* __restrict__ sW0,
    float* __restrict__ sW1, int bk, int bn, int tid)
{
    for (int v = tid; v < RK * RCOLS / 4; v += RTHREADS) {
        int k = v >> 5, n4 = (v & 31) * 4;
        float4 wv = __ldg((const float4*)&Wg[(long)(bk + k) * H_ + bn + n4]);
        const float we[4] = {wv.x, wv.y, wv.z, wv.w};
#pragma unroll
        for (int e = 0; e < 4; ++e) {
            uint32_t u0, u1;
            tf32_split(we[e], u0, u1);
            sW0[k * MPI + n4 + e] = __uint_as_float(u0);
            sW1[k * MPI + n4 + e] = __uint_as_float(u1);
        }
    }
}

// issue fused-h loads for one chunk: xw + (optionally) 8 partials
__device__ __forceinline__ void issue_loads(
    float4 raw[9], const float* __restrict__ xw,
    int row, int txw, int col0, bool hp, int pbuf)
{
    raw[0] = __ldcg((const float4*)&xw[((long)row * T_ + txw) * H_ + col0]);
    if (hp) {
#pragma unroll
        for (int qq = 0; qq < NSPLIT; ++qq)
            raw[1 + qq] = __ldcg(
                (const float4*)&g_part[pbuf][qq][(long)row * H_ + col0]);
    }
}

// sum + relu + tf32-split + store staged fragments (4 k-values of one row)
__device__ __forceinline__ void finalize_store(
    RecurSmem* __restrict__ sm, int buf, const float4 raw[9],
    bool hp, int m_s, int kq)
{
    float4 s = raw[0];
    if (hp) {
#pragma unroll
        for (int qq = 0; qq < NSPLIT; ++qq) {
            s.x += raw[1 + qq].x; s.y += raw[1 + qq].y;
            s.z += raw[1 + qq].z; s.w += raw[1 + qq].w;
        }
    }
    const float v[4] = {fmaxf(s.x, 0.f), fmaxf(s.y, 0.f),
                        fmaxf(s.z, 0.f), fmaxf(s.w, 0.f)};
    float* d0 = sm->A0 + buf * (CK * MPI);
    float* d1 = sm->A1 + buf * (CK * MPI);
#pragma unroll
    for (int e = 0; e < 4; ++e) {
        const int kl = kq + e;
        const int mcol = m_s ^ (((kl >> 3)) << 3);
        uint32_t u0, u1;
        tf32_split(v[e], u0, u1);
        d0[kl * MPI + mcol] = __uint_as_float(u0);
        d1[kl * MPI + mcol] = __uint_as_float(u1);
    }
}

// consume one staged chunk (2 k-steps) into the 32x32 warp tile fragments
__device__ __forceinline__ void consume_chunk(
    const RecurSmem* __restrict__ sm, int buf, int ch,
    int wr, int wc, int g, int tg, float c[2][4][4])
{
    const float* cA0 = sm->A0 + buf * (CK * MPI);
    const float* cA1 = sm->A1 + buf * (CK * MPI);
#pragma unroll
    for (int ks = 0; ks < 2; ++ks) {
        const int ka = ks * 8;              // staging k base
        const int kb = ch * CK + ks * 8;    // slab k base
        const int msw = ks << 3;
        uint32_t bt0[4][2], bt1[4][2];
#pragma unroll
        for (int in = 0; in < 4; ++in) {
            const int an = wc * 32 + in * 8 + g;
            bt0[in][0] = __float_as_uint(sm->W0[(kb + tg) * MPI + an]);
            bt0[in][1] = __float_as_uint(sm->W0[(kb + tg + 4) * MPI + an]);
            bt1[in][0] = __float_as_uint(sm->W1s[(kb + tg) * MPI + an]);
            bt1[in][1] = __float_as_uint(sm->W1s[(kb + tg + 4) * MPI + an]);
        }
#pragma unroll
        for (int im = 0; im < 2; ++im) {
            const int am  = (wr * 32 + im * 16 + g) ^ msw;
            const int am8 = (wr * 32 + im * 16 + g + 8) ^ msw;
            uint32_t a0[4], a1[4];
            a0[0] = __float_as_uint(cA0[(ka + tg) * MPI + am]);
            a0[1] = __float_as_uint(cA0[(ka + tg) * MPI + am8]);
            a0[2] = __float_as_uint(cA0[(ka + tg + 4) * MPI + am]);
            a0[3] = __float_as_uint(cA0[(ka + tg + 4) * MPI + am8]);
            a1[0] = __float_as_uint(cA1[(ka + tg) * MPI + am]);
            a1[1] = __float_as_uint(cA1[(ka + tg) * MPI + am8]);
            a1[2] = __float_as_uint(cA1[(ka + tg + 4) * MPI + am]);
            a1[3] = __float_as_uint(cA1[(ka + tg + 4) * MPI + am8]);
#pragma unroll
            for (int in = 0; in < 4; ++in) {
                mma_tf32(c[im][in], a0, bt1[in]);
                mma_tf32(c[im][in], a1, bt0[in]);
                mma_tf32(c[im][in], a0, bt0[in]);
            }
        }
    }
}

__device__ __forceinline__ void store_partials(
    float c[2][4][4], float* __restrict__ pq,
    int bm, int bn, int wr, int wc, int g, int tg)
{
#pragma unroll
    for (int im = 0; im < 2; ++im) {
        const int r0 = bm + wr * 32 + im * 16 + g;
#pragma unroll
        for (int in = 0; in < 4; ++in) {
            const int n0 = bn + wc * 32 + in * 8 + 2 * tg;
            __stcg((float2*)&pq[(long)r0 * H_ + n0],
                   make_float2(c[im][in][0], c[im][in][1]));
            __stcg((float2*)&pq[(long)(r0 + 8) * H_ + n0],
                   make_float2(c[im][in][2], c[im][in][3]));
        }
    }
}

__global__ void __launch_bounds__(RTHREADS, 1)
rnn_recur(const float* __restrict__ xw, const float* __restrict__ Wh,
          const float* __restrict__ W1, const float* __restrict__ b1,
          float* __restrict__ hid)
{
    extern __shared__ __align__(16) char smraw[];
    RecurSmem* sm = (RecurSmem*)smraw;

    const int tid = threadIdx.x;
    const int bid = blockIdx.x;
    const int q = bid & 7;
    const int c_ = (bid >> 3) & 7;
    const int r = bid >> 6;
    const int bm = r * RROWS, bn = c_ * RCOLS, bk = q * RK;

    const int wid = tid >> 5;
    const int wr = wid >> 2, wc = wid & 3;     // 4x4 warp grid, 32x32 tiles
    const int lane = tid & 31;
    const int g  = lane >> 2;
    const int tg = lane & 3;
    const int m_s = tid >> 2;                  // staging row 0..127
    const int kq  = (tid & 3) * 4;             // staging k offset {0,4,8,12}
    const int srow = bm + m_s;

    const int gtid = bid * RTHREADS + tid;     // 0..65535

    // pre-split Wh slab (resident for all 255 steps)
    split_slab(Wh, sm->W0, sm->W1s, bk, bn, tid);
    grid_sync();   // also orders xw availability semantics (prior kernel done)

    for (int t = 1; t < T_; ++t) {
        const int pbuf = t & 1;           // partials to READ (h_t)
        const int wbuf = (t + 1) & 1;     // partials to WRITE (h_{t+1})
        const bool hp = (t > 1);
        const int txw = t - 1;

        float4 raw[9];
        issue_loads(raw, xw, srow, txw, bk + kq, hp, pbuf);
        finalize_store(sm, 0, raw, hp, m_s, kq);
        __syncthreads();

        float cf[2][4][4];
#pragma unroll
        for (int i = 0; i < 2; ++i)
#pragma unroll
            for (int j = 0; j < 4; ++j)
#pragma unroll
                for (int e = 0; e < 4; ++e) cf[i][j][e] = 0.0f;

        for (int ch = 0; ch < NCHK; ++ch) {
            const int buf = ch & 1;
            if (ch + 1 < NCHK)
                issue_loads(raw, xw, srow, txw, bk + (ch + 1) * CK + kq, hp, pbuf);
            consume_chunk(sm, buf, ch, wr, wc, g, tg, cf);
            if (ch + 1 < NCHK)
                finalize_store(sm, buf ^ 1, raw, hp, m_s, kq);
            __syncthreads();
        }

        store_partials(cf, g_part[wbuf][q], bm, bn, wr, wc, g, tg);
        grid_sync();
    }

    // dense1: hid = relu(h_256 @ W1 + b1); h_256 partials live in buf 0
    split_slab(W1, sm->W0, sm->W1s, bk, bn, tid);
    __syncthreads();
    {
        const int pbuf = 0, wbuf = 1;
        const int txw = T_ - 1;
        float4 raw[9];
        issue_loads(raw, xw, srow, txw, bk + kq, true, pbuf);
        finalize_store(sm, 0, raw, true, m_s, kq);
        __syncthreads();

        float cf[2][4][4];
#pragma unroll
        for (int i = 0; i < 2; ++i)
#pragma unroll
            for (int j = 0; j < 4; ++j)
#pragma unroll
                for (int e = 0; e < 4; ++e) cf[i][j][e] = 0.0f;

        for (int ch = 0; ch < NCHK; ++ch) {
            const int buf = ch & 1;
            if (ch + 1 < NCHK)
                issue_loads(raw, xw, srow, txw, bk + (ch + 1) * CK + kq, true, pbuf);
            consume_chunk(sm, buf, ch, wr, wc, g, tg, cf);
            if (ch + 1 < NCHK)
                finalize_store(sm, buf ^ 1, raw, true, m_s, kq);
            __syncthreads();
        }
        store_partials(cf, g_part[wbuf][q], bm, bn, wr, wc, g, tg);
        grid_sync();

        // final reduce: hid = relu(b1 + sum_q part[1][q]) — one float4/thread
        {
            int m = gtid >> 8, n4 = (gtid & 255) * 4;
            long off = (long)m * H_ + n4;
            float4 s = __ldg((const float4*)&b1[n4]);
#pragma unroll
            for (int qq = 0; qq < NSPLIT; ++qq) {
                float4 p = __ldcg((const float4*)&g_part[1][qq][off]);
                s.x += p.x; s.y += p.y; s.z += p.z; s.w += p.w;
            }
            s.x = fmaxf(s.x, 0.f); s.y = fmaxf(s.y, 0.f);
            s.z = fmaxf(s.z, 0.f); s.w = fmaxf(s.w, 0.f);
            __stcg((float4*)&hid[off], s);
        }
    }
}

// ---------------- double-buffered SGEMM (dup-A; logits) ----------------------
template <int BM, int BN, int BK, int TM, int TN, int THREADS, bool RELU>
__global__ void __launch_bounds__(THREADS)
sgemm_kernel(int M, int N, int K,
             const float* __restrict__ A, int lda,
             const float* __restrict__ Bm, int ldb,
             const float* __restrict__ bias,
             float* __restrict__ C, int ldc)
{
    static_assert(TN % 4 == 0 && TM % 2 == 0, "");
    constexpr int TX = BN / TN;
    constexpr int TY = BM / TM;
    static_assert(TX * TY == THREADS, "");

    __shared__ __align__(16) unsigned long long As[2][BK][BM];
    __shared__ __align__(16) float Bs[2][BK][BN];

    const int tid = threadIdx.x;
    const int tx  = tid % TX;
    const int ty  = tid / TX;
    const int bm  = blockIdx.y * BM;
    const int bn  = blockIdx.x * BN;

    constexpr int A_VECS = BM * BK / 4;
    constexpr int A_PER  = A_VECS / THREADS;
    constexpr int B_VECS = BK * BN / 4;
    constexpr int B_PER  = B_VECS / THREADS;
    static_assert(A_VECS % THREADS == 0 && B_VECS % THREADS == 0, "");

    float4 aReg[A_PER];
    float4 bReg[B_PER];

    auto loadA = [&](int k0) {
#pragma unroll
        for (int i = 0; i < A_PER; ++i) {
            int v   = tid + i * THREADS;
            int row = v / (BK / 4);
            int kc  = (v % (BK / 4)) * 4;
            aReg[i] = *reinterpret_cast<const float4*>(
                &A[(long)(bm + row) * lda + k0 + kc]);
        }
    };
    auto loadB = [&](int k0) {
#pragma unroll
        for (int i = 0; i < B_PER; ++i) {
            int v    = tid + i * THREADS;
            int krow = v / (BN / 4);
            int nc   = (v % (BN / 4)) * 4;
            int col  = bn + nc;
            if (col < N)
                bReg[i] = *reinterpret_cast<const float4*>(
                    &Bm[(long)(k0 + krow) * ldb + col]);
            else
                bReg[i] = make_float4(0.f, 0.f, 0.f, 0.f);
        }
    };
    auto storeA = [&](int buf) {
#pragma unroll
        for (int i = 0; i < A_PER; ++i) {
            int v   = tid + i * THREADS;
            int row = v / (BK / 4);
            int kc  = (v % (BK / 4)) * 4;
            As[buf][kc + 0][row] = pack2(aReg[i].x, aReg[i].x);
            As[buf][kc + 1][row] = pack2(aReg[i].y, aReg[i].y);
            As[buf][kc + 2][row] = pack2(aReg[i].z, aReg[i].z);
            As[buf][kc + 3][row] = pack2(aReg[i].w, aReg[i].w);
        }
    };
    auto storeB = [&](int buf) {
#pragma unroll
        for (int i = 0; i < B_PER; ++i) {
            int v    = tid + i * THREADS;
            int krow = v / (BN / 4);
            int nc   = (v % (BN / 4)) * 4;
            *reinterpret_cast<float4*>(&Bs[buf][krow][nc]) = bReg[i];
        }
    };

    unsigned long long acc[TM][TN / 2];
#pragma unroll
    for (int i = 0; i < TM; ++i)
#pragma unroll
        for (int j = 0; j < TN / 2; ++j) acc[i][j] = 0ull;

    loadA(0); loadB(0);
    storeA(0); storeB(0);
    __syncthreads();

    const int nTiles = K / BK;
    for (int kt = 0; kt < nTiles; ++kt) {
        const int cur = kt & 1, nxt = cur ^ 1;
        if (kt + 1 < nTiles) { loadA((kt + 1) * BK); loadB((kt + 1) * BK); }

#pragma unroll
        for (int kk = 0; kk < BK; ++kk) {
            unsigned long long a2[TM];
#pragma unroll
            for (int i = 0; i < TM; i += 2) {
                ulonglong2 t = *reinterpret_cast<const ulonglong2*>(
                    &As[cur][kk][ty * TM + i]);
                a2[i] = t.x; a2[i + 1] = t.y;
            }
            unsigned long long b2[TN / 2];
#pragma unroll
            for (int j = 0; j < TN / 4; ++j) {
                ulonglong2 bv = *reinterpret_cast<const ulonglong2*>(
                    &Bs[cur][kk][tx * TN + 4 * j]);
                b2[2 * j] = bv.x; b2[2 * j + 1] = bv.y;
            }
#pragma unroll
            for (int i = 0; i < TM; ++i)
#pragma unroll
                for (int j = 0; j < TN / 2; ++j) ffma2(acc[i][j], a2[i], b2[j]);
        }

        if (kt + 1 < nTiles) { storeA(nxt); storeB(nxt); }
        __syncthreads();
    }

#pragma unroll
    for (int i = 0; i < TM; ++i) {
        const int m = bm + ty * TM + i;
#pragma unroll
        for (int j = 0; j < TN / 2; ++j) {
            float lo, hi;
            unpack2(acc[i][j], lo, hi);
            float v[2] = {lo, hi};
            const int n0 = bn + tx * TN + 2 * j;
#pragma unroll
            for (int e = 0; e < 2; ++e) {
                const int n = n0 + e;
                if (n < N) {
                    float cv = v[e];
                    if (bias) cv += bias[n];
                    if (RELU) cv = fmaxf(cv, 0.0f);
                    C[(long)m * ldc + n] = cv;
                }
            }
        }
    }
}

// ---------------- threefry2x32 / JAX gumbel ----------------------------------
__device__ __forceinline__ float gumbel_at(uint32_t idx) {
    const uint32_t k0 = 0u, k1 = 42u;
    const uint32_t ks2 = k0 ^ k1 ^ 0x1BD11BDAu;
    uint32_t x0 = k0;
    uint32_t x1 = idx + k1;
#define RND(r) { x0 += x1; x1 = ((x1 << (r)) | (x1 >> (32 - (r)))) ^ x0; }
    RND(13) RND(15) RND(26) RND(6)   x0 += k1;  x1 += ks2 + 1u;
    RND(17) RND(29) RND(16) RND(24)  x0 += ks2; x1 += k0 + 2u;
    RND(13) RND(15) RND(26) RND(6)   x0 += k0;  x1 += k1 + 3u;
    RND(17) RND(29) RND(16) RND(24)  x0 += k1;  x1 += ks2 + 4u;
    RND(13) RND(15) RND(26) RND(6)   x0 += ks2; x1 += k0 + 5u;
#undef RND
    const uint32_t bits = x0 ^ x1;
    float f = __uint_as_float((bits >> 9) | 0x3f800000u) - 1.0f;
    float u = fmaxf(f, 1.17549435e-38f);
    return -logf(-logf(u));
}

// ---------------- softmax+sample, finalize -----------------------------------
__global__ void sample_kernel() {
    const int b = blockIdx.x;
    const float* __restrict__ row = g_logits + (long)b * A_;
    const int tid = threadIdx.x;
    __shared__ float sred[256];
    __shared__ int   sidx[256];

    float mx = -3.402823466e38f;
    for (int a = tid; a < A_; a += 256) mx = fmaxf(mx, row[a]);
    sred[tid] = mx; __syncthreads();
    for (int s = 128; s; s >>= 1) {
        if (tid < s) sred[tid] = fmaxf(sred[tid], sred[tid + s]);
        __syncthreads();
    }
    const float rmax = sred[0]; __syncthreads();

    float sum = 0.f;
    for (int a = tid; a < A_; a += 256) sum += expf(row[a] - rmax);
    sred[tid] = sum; __syncthreads();
    for (int s = 128; s; s >>= 1) {
        if (tid < s) sred[tid] += sred[tid + s];
        __syncthreads();
    }
    const float rsum = sred[0]; __syncthreads();

    float bestv = -3.402823466e38f;
    int   besti = A_;
    for (int a = tid; a < A_; a += 256) {
        float p = expf(row[a] - rmax) / rsum;
        float v = p + gumbel_at((uint32_t)(b * A_ + a));
        if (v > bestv) { bestv = v; besti = a; }
    }
    sred[tid] = bestv; sidx[tid] = besti; __syncthreads();
    for (int s = 128; s; s >>= 1) {
        if (tid < s) {
            float v2 = sred[tid + s]; int i2 = sidx[tid + s];
            if (v2 > sred[tid] || (v2 == sred[tid] && i2 < sidx[tid])) {
                sred[tid] = v2; sidx[tid] = i2;
            }
        }
        __syncthreads();
    }
    if (tid == 0) {
        const int a = sidx[0];
        g_action[b] = a;
        float p = expf(row[a] - rmax) / rsum;
        p = fminf(fmaxf(p, 1e-7f), 1.0f - 1e-7f);
        g_rowloss[b] = -logf(p);
    }
}

__global__ void finalize_kernel(float* __restrict__ out, int out_size) {
    const int tid = threadIdx.x;
    __shared__ float red[256];
    red[tid] = g_rowloss[tid];
    __syncthreads();
    for (int s = 128; s; s >>= 1) {
        if (tid < s) red[tid] += red[tid + s];
        __syncthreads();
    }
    const float loss = red[0] / (float)B_;

    if (out_size == 1) {
        if (tid == 0) out[0] = loss;
        return;
    }
    if (tid < B_ && tid < out_size) out[tid] = (float)g_action[tid];
    if (tid == 0 && out_size > B_) out[B_] = loss;
    for (int i = B_ + 1 + tid; i < out_size; i += 256) out[i] = 0.0f;
}

// ---------------- launch -----------------------------------------------------
extern "C" void kernel_launch(void* const* d_in, const int* in_sizes, int n_in,
                              void* d_out, int out_size) {
    const float* inputs = (const float*)d_in[0];
    const float* Wx     = (const float*)d_in[1];
    const float* Wh     = (const float*)d_in[2];
    const float* b_rnn  = (const float*)d_in[3];
    const float* W1     = (const float*)d_in[4];
    const float* b1     = (const float*)d_in[5];
    const float* W2     = (const float*)d_in[6];
    const float* b2     = (const float*)d_in[7];

    float *xw, *hid, *logits;
    cudaGetSymbolAddress((void**)&xw,     g_xw);
    cudaGetSymbolAddress((void**)&hid,    g_hid);
    cudaGetSymbolAddress((void**)&logits, g_logits);

    // xw = inputs @ Wx + b_rnn  — 3xTF32 tensor-core GEMM
    const int ga_smem = 8 * GA_TILE * 4;
    cudaFuncSetAttribute(gemm_a_mma,
                         cudaFuncAttributeMaxDynamicSharedMemorySize, ga_smem);
    gemm_a_mma<<<dim3(H_ / 128, (B_ * T_) / 128), 256, ga_smem>>>(
        inputs, Wx, b_rnn, xw);

    // persistent recurrence + fused dense1 — fused-reduce 3xTF32 mma
    const int smem = (int)sizeof(RecurSmem);   // 174080
    cudaFuncSetAttribute(rnn_recur, cudaFuncAttributeMaxDynamicSharedMemorySize, smem);
    rnn_recur<<<NBLK, RTHREADS, smem>>>(xw, Wh, W1, b1, hid);

    // logits = hid @ W2 + b2   (N=1000, ragged)
    sgemm_kernel<32, 64, 16, 4, 4, 128, false>
        <<<dim3((A_ + 63) / 64, B_ / 32), 128>>>(
            B_, A_, H_, hid, H_, W2, A_, b2, logits, A_);

    sample_kernel<<<B_, 256>>>();
    finalize_kernel<<<1, 256>>>((float*)d_out, out_size);
}

// round 16
// speedup vs baseline: 1.2673x; 1.2673x over previous
#include <cuda_runtime.h>
#include <cuda_bf16.h>
#include <cstdint>

#define B_ 256
#define T_ 256
#define F_ 512
#define H_ 1024
#define A_ 1000

// recurrence: 128 blocks = 2 row-groups(128) x 8 col-groups(128) x 8 k-splits(128)
#define NBLK 128
#define RTHREADS 512
#define RROWS 128
#define RCOLS 128
#define RK    128
#define NSPLIT 8
#define MPI   136   // smem pitch (floats): conflict-free mma fragment access

// ---------------- scratch (static device globals; no allocation) -------------
__device__ float g_xw[(size_t)B_ * T_ * H_];     // input projection [B][T][H]
__device__ float g_hbuf[B_ * H_];                // hidden state
__device__ float g_part[NSPLIT][B_ * H_];        // k-split partials [q][m][n]
__device__ float g_hid[B_ * H_];
__device__ float g_logits[B_ * A_];
__device__ int   g_action[B_];
__device__ float g_rowloss[B_];

// grid barrier state (self-cleaning; safe across graph replays)
__device__ unsigned g_cnt = 0;
__device__ volatile unsigned g_gen = 0;

// ---------------- packed fp32x2 FMA helpers (sgemm for logits) ---------------
__device__ __forceinline__ unsigned long long pack2(float lo, float hi) {
    unsigned long long r;
    asm("mov.b64 %0, {%1, %2};" : "=l"(r) : "f"(lo), "f"(hi));
    return r;
}
__device__ __forceinline__ void unpack2(unsigned long long v, float& lo, float& hi) {
    asm("mov.b64 {%0, %1}, %2;" : "=f"(lo), "=f"(hi) : "l"(v));
}
__device__ __forceinline__ void ffma2(unsigned long long& d, unsigned long long a,
                                      unsigned long long b) {
    asm("fma.rn.f32x2 %0, %1, %2, %0;" : "+l"(d) : "l"(a), "l"(b));
}

// ---------------- tf32 split + mma.sync helpers ------------------------------
__device__ __forceinline__ void tf32_split(float x, uint32_t& u0, uint32_t& u1) {
    asm("cvt.rna.tf32.f32 %0, %1;" : "=r"(u0) : "f"(x));
    float r = x - __uint_as_float(u0);
    asm("cvt.rna.tf32.f32 %0, %1;" : "=r"(u1) : "f"(r));
}
__device__ __forceinline__ void mma_tf32(float c[4], const uint32_t a[4],
                                         const uint32_t b[2]) {
    asm volatile(
        "mma.sync.aligned.m16n8k8.row.col.f32.tf32.tf32.f32 "
        "{%0,%1,%2,%3}, {%4,%5,%6,%7}, {%8,%9}, {%0,%1,%2,%3};"
        : "+f"(c[0]), "+f"(c[1]), "+f"(c[2]), "+f"(c[3])
        : "r"(a[0]), "r"(a[1]), "r"(a[2]), "r"(a[3]), "r"(b[0]), "r"(b[1]));
}

// ---------------- phase-A 3xTF32 tensor GEMM ---------------------------------
// xw[65536,1024] = inputs[65536,512] @ Wx[512,1024] + b_rnn
// CTA tile 128x128, 8 warps (2x4), warp tile 64x32, K-chunks of 16, dbl-buffered.
// Term-major MMA issue: same-accumulator MMAs are 4 apart (latency cover).
#define PITA 136
#define GA_CH 16
#define GA_NCH (F_ / GA_CH)        // 32 chunks
#define GA_TILE (GA_CH * PITA)

__global__ void __launch_bounds__(256, 1)
gemm_a_mma(const float* __restrict__ Ag, const float* __restrict__ Bg,
           const float* __restrict__ bias, float* __restrict__ C)
{
    extern __shared__ __align__(16) float sm[];
    float* sA0 = sm;
    float* sA1 = sm + 2 * GA_TILE;
    float* sB0 = sm + 4 * GA_TILE;
    float* sB1 = sm + 6 * GA_TILE;

    const int tid  = threadIdx.x;
    const int lane = tid & 31;
    const int w    = tid >> 5;
    const int wm   = w >> 2;
    const int wn   = w & 3;
    const int bm   = blockIdx.y * 128;
    const int bn   = blockIdx.x * 128;
    const int g    = lane >> 2;
    const int tg   = lane & 3;

    const int a_k4  = tid >> 7;
    const int a_row = tid & 127;
    const int b_k   = tid >> 5;
    const int b_n4  = lane;

    float4 aReg[2], bReg[2];
    auto loadG = [&](int k0) {
#pragma unroll
        for (int j = 0; j < 2; ++j) {
            aReg[j] = __ldg((const float4*)(Ag + (size_t)(bm + a_row) * F_ +
                                            k0 + (a_k4 + 2 * j) * 4));
            bReg[j] = __ldg((const float4*)(Bg + (size_t)(k0 + b_k + 8 * j) * H_ +
                                            bn + b_n4 * 4));
        }
    };
    auto storeS = [&](int buf) {
        float* dA0 = sA0 + buf * GA_TILE;
        float* dA1 = sA1 + buf * GA_TILE;
        float* dB0 = sB0 + buf * GA_TILE;
        float* dB1 = sB1 + buf * GA_TILE;
#pragma unroll
        for (int j = 0; j < 2; ++j) {
            const int kb = (a_k4 + 2 * j) * 4;
            const float av[4] = {aReg[j].x, aReg[j].y, aReg[j].z, aReg[j].w};
#pragma unroll
            for (int e = 0; e < 4; ++e) {
                uint32_t u0, u1;
                tf32_split(av[e], u0, u1);
                dA0[(kb + e) * PITA + a_row] = __uint_as_float(u0);
                dA1[(kb + e) * PITA + a_row] = __uint_as_float(u1);
            }
            const int kr = b_k + 8 * j;
            const float bv[4] = {bReg[j].x, bReg[j].y, bReg[j].z, bReg[j].w};
            uint4 q0, q1;
            uint32_t* p0 = (uint32_t*)&q0;
            uint32_t* p1 = (uint32_t*)&q1;
#pragma unroll
            for (int e = 0; e < 4; ++e) tf32_split(bv[e], p0[e], p1[e]);
            *(uint4*)(dB0 + kr * PITA + b_n4 * 4) = q0;
            *(uint4*)(dB1 + kr * PITA + b_n4 * 4) = q1;
        }
    };

    float c[4][4][4];
#pragma unroll
    for (int i = 0; i < 4; ++i)
#pragma unroll
        for (int j = 0; j < 4; ++j)
#pragma unroll
            for (int e = 0; e < 4; ++e) c[i][j][e] = 0.0f;

    loadG(0);
    storeS(0);
    __syncthreads();

    for (int kt = 0; kt < GA_NCH; ++kt) {
        const int cur = kt & 1;
        if (kt + 1 < GA_NCH) loadG((kt + 1) * GA_CH);

        const float* cA0 = sA0 + cur * GA_TILE;
        const float* cA1 = sA1 + cur * GA_TILE;
        const float* cB0 = sB0 + cur * GA_TILE;
        const float* cB1 = sB1 + cur * GA_TILE;

#pragma unroll
        for (int s = 0; s < 2; ++s) {
            const int ko = s * 8;
            uint32_t bt0[4][2], bt1[4][2];
#pragma unroll
            for (int in = 0; in < 4; ++in) {
                const int an = wn * 32 + in * 8 + g;
                bt0[in][0] = __float_as_uint(cB0[(ko + tg) * PITA + an]);
                bt0[in][1] = __float_as_uint(cB0[(ko + tg + 4) * PITA + an]);
                bt1[in][0] = __float_as_uint(cB1[(ko + tg) * PITA + an]);
                bt1[in][1] = __float_as_uint(cB1[(ko + tg + 4) * PITA + an]);
            }
#pragma unroll
            for (int im = 0; im < 4; ++im) {
                const int am = wm * 64 + im * 16 + g;
                uint32_t a0[4], a1[4];
                a0[0] = __float_as_uint(cA0[(ko + tg) * PITA + am]);
                a0[1] = __float_as_uint(cA0[(ko + tg) * PITA + am + 8]);
                a0[2] = __float_as_uint(cA0[(ko + tg + 4) * PITA + am]);
                a0[3] = __float_as_uint(cA0[(ko + tg + 4) * PITA + am + 8]);
                a1[0] = __float_as_uint(cA1[(ko + tg) * PITA + am]);
                a1[1] = __float_as_uint(cA1[(ko + tg) * PITA + am + 8]);
                a1[2] = __float_as_uint(cA1[(ko + tg + 4) * PITA + am]);
                a1[3] = __float_as_uint(cA1[(ko + tg + 4) * PITA + am + 8]);
                // term-major issue: same-accumulator MMAs 4 apart, order
                // per accumulator preserved (t1,t2,t3) -> bit-identical
#pragma unroll
                for (int in = 0; in < 4; ++in) mma_tf32(c[im][in], a0, bt1[in]);
#pragma unroll
                for (int in = 0; in < 4; ++in) mma_tf32(c[im][in], a1, bt0[in]);
#pragma unroll
                for (int in = 0; in < 4; ++in) mma_tf32(c[im][in], a0, bt0[in]);
            }
        }

        if (kt + 1 < GA_NCH) storeS(cur ^ 1);
        __syncthreads();
    }

#pragma unroll
    for (int im = 0; im < 4; ++im) {
        const int r0 = bm + wm * 64 + im * 16 + g;
#pragma unroll
        for (int in = 0; in < 4; ++in) {
            const int n0 = bn + wn * 32 + in * 8 + 2 * tg;
            float2 bv = *(const float2*)&bias[n0];
            float2 o0 = {c[im][in][0] + bv.x, c[im][in][1] + bv.y};
            float2 o1 = {c[im][in][2] + bv.x, c[im][in][3] + bv.y};
            *(float2*)&C[(size_t)r0 * H_ + n0]       = o0;
            *(float2*)&C[(size_t)(r0 + 8) * H_ + n0] = o1;
        }
    }
}

// ---------------- grid-wide barrier ------------------------------------------
__device__ __forceinline__ void grid_sync() {
    __syncthreads();
    if (threadIdx.x == 0) {
        __threadfence();
        unsigned gen = g_gen;
        unsigned old = atomicAdd(&g_cnt, 1u);
        if (old == NBLK - 1) {
            g_cnt = 0;
            __threadfence();
            g_gen = gen + 1;
        } else {
            while (g_gen == gen) { }
            __threadfence();
        }
    }
    __syncthreads();
}

// ---------------- persistent recurrence kernel: 3xTF32 mma -------------------
// (Round-13 structure restored: h materialized, 2 barriers/step, separate
//  reduce, 512 threads, 16 warps 4x4, 4 chunks of 32 k. Only change: MMA
//  issue is term-major for latency cover.)

struct RecurSmem {
    float W0[RK * MPI];          // 69632 B
    float W1s[RK * MPI];         // 69632 B
    float A0[2 * 32 * MPI];      // 34816 B (2 staging buffers, term 0)
    float A1[2 * 32 * MPI];      // 34816 B (term 1)
};                               // total 208896 B

__device__ __forceinline__ void split_slab(
    const float* __restrict__ Wg, float* __restrict__ sW0,
    float* __restrict__ sW1, int bk, int bn, int tid)
{
    for (int v = tid; v < RK * RCOLS / 4; v += RTHREADS) {
        int k = v >> 5, n4 = (v & 31) * 4;
        float4 wv = __ldg((const float4*)&Wg[(long)(bk + k) * H_ + bn + n4]);
        const float we[4] = {wv.x, wv.y, wv.z, wv.w};
#pragma unroll
        for (int e = 0; e < 4; ++e) {
            uint32_t u0, u1;
            tf32_split(we[e], u0, u1);
            sW0[k * MPI + n4 + e] = __uint_as_float(u0);
            sW1[k * MPI + n4 + e] = __uint_as_float(u1);
        }
    }
}

__device__ __forceinline__ void stage_chunk(
    float* __restrict__ sA0, float* __restrict__ sA1, int buf,
    int kq, int mcol, const float4 va[2])
{
    float* d0 = sA0 + buf * (32 * MPI);
    float* d1 = sA1 + buf * (32 * MPI);
#pragma unroll
    for (int j = 0; j < 2; ++j) {
        const float v[4] = {va[j].x, va[j].y, va[j].z, va[j].w};
#pragma unroll
        for (int e = 0; e < 4; ++e) {
            uint32_t u0, u1;
            tf32_split(v[e], u0, u1);
            const int kl = kq + j * 4 + e;
            d0[kl * MPI + mcol] = __uint_as_float(u0);
            d1[kl * MPI + mcol] = __uint_as_float(u1);
        }
    }
}

// full 128x128x128 tile GEMM: h (global) x resident slab -> c fragments
__device__ __forceinline__ void mma_tile(
    const float* __restrict__ hrow,            // &h[(bm+m_s)*H_ + bk + kq]
    const float* __restrict__ sW0, const float* __restrict__ sW1,
    float* __restrict__ sA0, float* __restrict__ sA1,
    int wr, int wc, int g, int tg, int mcol, int kq,
    float c[2][4][4])
{
    float4 va[2];
    va[0] = __ldcg((const float4*)(hrow));
    va[1] = __ldcg((const float4*)(hrow + 4));
    stage_chunk(sA0, sA1, 0, kq, mcol, va);
    __syncthreads();

    for (int ch = 0; ch < 4; ++ch) {
        const int buf = ch & 1;
        if (ch < 3) {
            va[0] = __ldcg((const float4*)(hrow + (ch + 1) * 32));
            va[1] = __ldcg((const float4*)(hrow + (ch + 1) * 32 + 4));
        }

        const float* cA0 = sA0 + buf * (32 * MPI);
        const float* cA1 = sA1 + buf * (32 * MPI);
#pragma unroll
        for (int ks = 0; ks < 4; ++ks) {
            const int kb = ch * 32 + ks * 8;   // slab (B) k
            const int ka = ks * 8;             // staging (A) k
            const int msw = ks << 3;
            uint32_t bt0[4][2], bt1[4][2];
#pragma unroll
            for (int in = 0; in < 4; ++in) {
                const int an = wc * 32 + in * 8 + g;
                bt0[in][0] = __float_as_uint(sW0[(kb + tg) * MPI + an]);
                bt0[in][1] = __float_as_uint(sW0[(kb + tg + 4) * MPI + an]);
                bt1[in][0] = __float_as_uint(sW1[(kb + tg) * MPI + an]);
                bt1[in][1] = __float_as_uint(sW1[(kb + tg + 4) * MPI + an]);
            }
#pragma unroll
            for (int im = 0; im < 2; ++im) {
                const int am  = (wr * 32 + im * 16 + g) ^ msw;
                const int am8 = (wr * 32 + im * 16 + g + 8) ^ msw;
                uint32_t a0[4], a1[4];
                a0[0] = __float_as_uint(cA0[(ka + tg) * MPI + am]);
                a0[1] = __float_as_uint(cA0[(ka + tg) * MPI + am8]);
                a0[2] = __float_as_uint(cA0[(ka + tg + 4) * MPI + am]);
                a0[3] = __float_as_uint(cA0[(ka + tg + 4) * MPI + am8]);
                a1[0] = __float_as_uint(cA1[(ka + tg) * MPI + am]);
                a1[1] = __float_as_uint(cA1[(ka + tg) * MPI + am8]);
                a1[2] = __float_as_uint(cA1[(ka + tg + 4) * MPI + am]);
                a1[3] = __float_as_uint(cA1[(ka + tg + 4) * MPI + am8]);
                // term-major issue: same-accumulator MMAs 4 apart, per-
                // accumulator term order preserved -> bit-identical result
#pragma unroll
                for (int in = 0; in < 4; ++in) mma_tf32(c[im][in], a0, bt1[in]);
#pragma unroll
                for (int in = 0; in < 4; ++in) mma_tf32(c[im][in], a1, bt0[in]);
#pragma unroll
                for (int in = 0; in < 4; ++in) mma_tf32(c[im][in], a0, bt0[in]);
            }
        }

        if (ch < 3) stage_chunk(sA0, sA1, buf ^ 1, kq, mcol, va);
        __syncthreads();
    }
}

__device__ __forceinline__ void store_partials(
    float c[2][4][4], float* __restrict__ pq,
    int bm, int bn, int wr, int wc, int g, int tg)
{
#pragma unroll
    for (int im = 0; im < 2; ++im) {
        const int r0 = bm + wr * 32 + im * 16 + g;
#pragma unroll
        for (int in = 0; in < 4; ++in) {
            const int n0 = bn + wc * 32 + in * 8 + 2 * tg;
            __stcg((float2*)&pq[(long)r0 * H_ + n0],
                   make_float2(c[im][in][0], c[im][in][1]));
            __stcg((float2*)&pq[(long)(r0 + 8) * H_ + n0],
                   make_float2(c[im][in][2], c[im][in][3]));
        }
    }
}

__global__ void __launch_bounds__(RTHREADS, 1)
rnn_recur(const float* __restrict__ xw, const float* __restrict__ Wh,
          const float* __restrict__ W1, const float* __restrict__ b1,
          float* __restrict__ h, float* __restrict__ hid)
{
    extern __shared__ __align__(16) char smraw[];
    RecurSmem* sm = (RecurSmem*)smraw;

    const int tid = threadIdx.x;
    const int bid = blockIdx.x;
    const int q = bid & 7;
    const int c_ = (bid >> 3) & 7;
    const int r = bid >> 6;
    const int bm = r * RROWS, bn = c_ * RCOLS, bk = q * RK;

    const int w  = tid >> 5;
    const int wr = w >> 2, wc = w & 3;
    const int lane = tid & 31;
    const int g  = lane >> 2;
    const int tg = lane & 3;

    // staging mapping
    const int m_s = tid >> 2;          // 0..127
    const int kq  = (tid & 3) * 8;     // {0,8,16,24}
    const int mcol = m_s ^ ((tid & 3) << 3);   // XOR swizzle, (tid&3) == kl>>3

    const int gtid = bid * RTHREADS + tid;
    const int rm = gtid >> 8;
    const int rn4 = (gtid & 255) * 4;
    const long roff = (long)rm * H_ + rn4;

    // pre-split Wh slab (resident for all 255 steps)
    split_slab(Wh, sm->W0, sm->W1s, bk, bn, tid);

    // h_1 = relu(xw[:,0,:])
    {
        float4 v = __ldg((const float4*)&xw[((long)rm * T_ + 0) * H_ + rn4]);
        v.x = fmaxf(v.x, 0.f); v.y = fmaxf(v.y, 0.f);
        v.z = fmaxf(v.z, 0.f); v.w = fmaxf(v.w, 0.f);
        __stcg((float4*)&h[roff], v);
    }
    grid_sync();

    for (int t = 1; t < T_; ++t) {
        float4 xv = __ldcg((const float4*)&xw[((long)rm * T_ + t) * H_ + rn4]);

        float cf[2][4][4];
#pragma unroll
        for (int i = 0; i < 2; ++i)
#pragma unroll
            for (int j = 0; j < 4; ++j)
#pragma unroll
                for (int e = 0; e < 4; ++e) cf[i][j][e] = 0.0f;

        mma_tile(&h[(long)(bm + m_s) * H_ + bk + kq], sm->W0, sm->W1s,
                 sm->A0, sm->A1, wr, wc, g, tg, mcol, kq, cf);
        store_partials(cf, g_part[q], bm, bn, wr, wc, g, tg);
        grid_sync();

        // reduce: h = relu(xw[:,t,:] + sum_q partial_q)
        {
            float4 s = xv;
#pragma unroll
            for (int qq = 0; qq < NSPLIT; ++qq) {
                float4 p = __ldcg((const float4*)&g_part[qq][roff]);
                s.x += p.x; s.y += p.y; s.z += p.z; s.w += p.w;
            }
            s.x = fmaxf(s.x, 0.f); s.y = fmaxf(s.y, 0.f);
            s.z = fmaxf(s.z, 0.f); s.w = fmaxf(s.w, 0.f);
            __stcg((float4*)&h[roff], s);
        }
        grid_sync();
    }
    // h now holds h_last (h_256)

    // fused dense1: hid = relu(h_last @ W1 + b1) — re-split slab from W1
    split_slab(W1, sm->W0, sm->W1s, bk, bn, tid);
    __syncthreads();
    {
        float cf[2][4][4];
#pragma unroll
        for (int i = 0; i < 2; ++i)
#pragma unroll
            for (int j = 0; j < 4; ++j)
#pragma unroll
                for (int e = 0; e < 4; ++e) cf[i][j][e] = 0.0f;
        mma_tile(&h[(long)(bm + m_s) * H_ + bk + kq], sm->W0, sm->W1s,
                 sm->A0, sm->A1, wr, wc, g, tg, mcol, kq, cf);
        store_partials(cf, g_part[q], bm, bn, wr, wc, g, tg);
        grid_sync();
        {
            float4 s = __ldg((const float4*)&b1[rn4]);
#pragma unroll
            for (int qq = 0; qq < NSPLIT; ++qq) {
                float4 p = __ldcg((const float4*)&g_part[qq][roff]);
                s.x += p.x; s.y += p.y; s.z += p.z; s.w += p.w;
            }
            s.x = fmaxf(s.x, 0.f); s.y = fmaxf(s.y, 0.f);
            s.z = fmaxf(s.z, 0.f); s.w = fmaxf(s.w, 0.f);
            __stcg((float4*)&hid[roff], s);
        }
    }
}

// ---------------- double-buffered SGEMM (dup-A; logits) ----------------------
template <int BM, int BN, int BK, int TM, int TN, int THREADS, bool RELU>
__global__ void __launch_bounds__(THREADS)
sgemm_kernel(int M, int N, int K,
             const float* __restrict__ A, int lda,
             const float* __restrict__ Bm, int ldb,
             const float* __restrict__ bias,
             float* __restrict__ C, int ldc)
{
    static_assert(TN % 4 == 0 && TM % 2 == 0, "");
    constexpr int TX = BN / TN;
    constexpr int TY = BM / TM;
    static_assert(TX * TY == THREADS, "");

    __shared__ __align__(16) unsigned long long As[2][BK][BM];
    __shared__ __align__(16) float Bs[2][BK][BN];

    const int tid = threadIdx.x;
    const int tx  = tid % TX;
    const int ty  = tid / TX;
    const int bm  = blockIdx.y * BM;
    const int bn  = blockIdx.x * BN;

    constexpr int A_VECS = BM * BK / 4;
    constexpr int A_PER  = A_VECS / THREADS;
    constexpr int B_VECS = BK * BN / 4;
    constexpr int B_PER  = B_VECS / THREADS;
    static_assert(A_VECS % THREADS == 0 && B_VECS % THREADS == 0, "");

    float4 aReg[A_PER];
    float4 bReg[B_PER];

    auto loadA = [&](int k0) {
#pragma unroll
        for (int i = 0; i < A_PER; ++i) {
            int v   = tid + i * THREADS;
            int row = v / (BK / 4);
            int kc  = (v % (BK / 4)) * 4;
            aReg[i] = *reinterpret_cast<const float4*>(
                &A[(long)(bm + row) * lda + k0 + kc]);
        }
    };
    auto loadB = [&](int k0) {
#pragma unroll
        for (int i = 0; i < B_PER; ++i) {
            int v    = tid + i * THREADS;
            int krow = v / (BN / 4);
            int nc   = (v % (BN / 4)) * 4;
            int col  = bn + nc;
            if (col < N)
                bReg[i] = *reinterpret_cast<const float4*>(
                    &Bm[(long)(k0 + krow) * ldb + col]);
            else
                bReg[i] = make_float4(0.f, 0.f, 0.f, 0.f);
        }
    };
    auto storeA = [&](int buf) {
#pragma unroll
        for (int i = 0; i < A_PER; ++i) {
            int v   = tid + i * THREADS;
            int row = v / (BK / 4);
            int kc  = (v % (BK / 4)) * 4;
            As[buf][kc + 0][row] = pack2(aReg[i].x, aReg[i].x);
            As[buf][kc + 1][row] = pack2(aReg[i].y, aReg[i].y);
            As[buf][kc + 2][row] = pack2(aReg[i].z, aReg[i].z);
            As[buf][kc + 3][row] = pack2(aReg[i].w, aReg[i].w);
        }
    };
    auto storeB = [&](int buf) {
#pragma unroll
        for (int i = 0; i < B_PER; ++i) {
            int v    = tid + i * THREADS;
            int krow = v / (BN / 4);
            int nc   = (v % (BN / 4)) * 4;
            *reinterpret_cast<float4*>(&Bs[buf][krow][nc]) = bReg[i];
        }
    };

    unsigned long long acc[TM][TN / 2];
#pragma unroll
    for (int i = 0; i < TM; ++i)
#pragma unroll
        for (int j = 0; j < TN / 2; ++j) acc[i][j] = 0ull;

    loadA(0); loadB(0);
    storeA(0); storeB(0);
    __syncthreads();

    const int nTiles = K / BK;
    for (int kt = 0; kt < nTiles; ++kt) {
        const int cur = kt & 1, nxt = cur ^ 1;
        if (kt + 1 < nTiles) { loadA((kt + 1) * BK); loadB((kt + 1) * BK); }

#pragma unroll
        for (int kk = 0; kk < BK; ++kk) {
            unsigned long long a2[TM];
#pragma unroll
            for (int i = 0; i < TM; i += 2) {
                ulonglong2 t = *reinterpret_cast<const ulonglong2*>(
                    &As[cur][kk][ty * TM + i]);
                a2[i] = t.x; a2[i + 1] = t.y;
            }
            unsigned long long b2[TN / 2];
#pragma unroll
            for (int j = 0; j < TN / 4; ++j) {
                ulonglong2 bv = *reinterpret_cast<const ulonglong2*>(
                    &Bs[cur][kk][tx * TN + 4 * j]);
                b2[2 * j] = bv.x; b2[2 * j + 1] = bv.y;
            }
#pragma unroll
            for (int i = 0; i < TM; ++i)
#pragma unroll
                for (int j = 0; j < TN / 2; ++j) ffma2(acc[i][j], a2[i], b2[j]);
        }

        if (kt + 1 < nTiles) { storeA(nxt); storeB(nxt); }
        __syncthreads();
    }

#pragma unroll
    for (int i = 0; i < TM; ++i) {
        const int m = bm + ty * TM + i;
#pragma unroll
        for (int j = 0; j < TN / 2; ++j) {
            float lo, hi;
            unpack2(acc[i][j], lo, hi);
            float v[2] = {lo, hi};
            const int n0 = bn + tx * TN + 2 * j;
#pragma unroll
            for (int e = 0; e < 2; ++e) {
                const int n = n0 + e;
                if (n < N) {
                    float cv = v[e];
                    if (bias) cv += bias[n];
                    if (RELU) cv = fmaxf(cv, 0.0f);
                    C[(long)m * ldc + n] = cv;
                }
            }
        }
    }
}

// ---------------- threefry2x32 / JAX gumbel ----------------------------------
__device__ __forceinline__ float gumbel_at(uint32_t idx) {
    const uint32_t k0 = 0u, k1 = 42u;
    const uint32_t ks2 = k0 ^ k1 ^ 0x1BD11BDAu;
    uint32_t x0 = k0;
    uint32_t x1 = idx + k1;
#define RND(r) { x0 += x1; x1 = ((x1 << (r)) | (x1 >> (32 - (r)))) ^ x0; }
    RND(13) RND(15) RND(26) RND(6)   x0 += k1;  x1 += ks2 + 1u;
    RND(17) RND(29) RND(16) RND(24)  x0 += ks2; x1 += k0 + 2u;
    RND(13) RND(15) RND(26) RND(6)   x0 += k0;  x1 += k1 + 3u;
    RND(17) RND(29) RND(16) RND(24)  x0 += k1;  x1 += ks2 + 4u;
    RND(13) RND(15) RND(26) RND(6)   x0 += ks2; x1 += k0 + 5u;
#undef RND
    const uint32_t bits = x0 ^ x1;
    float f = __uint_as_float((bits >> 9) | 0x3f800000u) - 1.0f;
    float u = fmaxf(f, 1.17549435e-38f);
    return -logf(-logf(u));
}

// ---------------- softmax+sample, finalize -----------------------------------
__global__ void sample_kernel() {
    const int b = blockIdx.x;
    const float* __restrict__ row = g_logits + (long)b * A_;
    const int tid = threadIdx.x;
    __shared__ float sred[256];
    __shared__ int   sidx[256];

    float mx = -3.402823466e38f;
    for (int a = tid; a < A_; a += 256) mx = fmaxf(mx, row[a]);
    sred[tid] = mx; __syncthreads();
    for (int s = 128; s; s >>= 1) {
        if (tid < s) sred[tid] = fmaxf(sred[tid], sred[tid + s]);
        __syncthreads();
    }
    const float rmax = sred[0]; __syncthreads();

    float sum = 0.f;
    for (int a = tid; a < A_; a += 256) sum += expf(row[a] - rmax);
    sred[tid] = sum; __syncthreads();
    for (int s = 128; s; s >>= 1) {
        if (tid < s) sred[tid] += sred[tid + s];
        __syncthreads();
    }
    const float rsum = sred[0]; __syncthreads();

    float bestv = -3.402823466e38f;
    int   besti = A_;
    for (int a = tid; a < A_; a += 256) {
        float p = expf(row[a] - rmax) / rsum;
        float v = p + gumbel_at((uint32_t)(b * A_ + a));
        if (v > bestv) { bestv = v; besti = a; }
    }
    sred[tid] = bestv; sidx[tid] = besti; __syncthreads();
    for (int s = 128; s; s >>= 1) {
        if (tid < s) {
            float v2 = sred[tid + s]; int i2 = sidx[tid + s];
            if (v2 > sred[tid] || (v2 == sred[tid] && i2 < sidx[tid])) {
                sred[tid] = v2; sidx[tid] = i2;
            }
        }
        __syncthreads();
    }
    if (tid == 0) {
        const int a = sidx[0];
        g_action[b] = a;
        float p = expf(row[a] - rmax) / rsum;
        p = fminf(fmaxf(p, 1e-7f), 1.0f - 1e-7f);
        g_rowloss[b] = -logf(p);
    }
}

__global__ void finalize_kernel(float* __restrict__ out, int out_size) {
    const int tid = threadIdx.x;
    __shared__ float red[256];
    red[tid] = g_rowloss[tid];
    __syncthreads();
    for (int s = 128; s; s >>= 1) {
        if (tid < s) red[tid] += red[tid + s];
        __syncthreads();
    }
    const float loss = red[0] / (float)B_;

    if (out_size == 1) {
        if (tid == 0) out[0] = loss;
        return;
    }
    if (tid < B_ && tid < out_size) out[tid] = (float)g_action[tid];
    if (tid == 0 && out_size > B_) out[B_] = loss;
    for (int i = B_ + 1 + tid; i < out_size; i += 256) out[i] = 0.0f;
}

// ---------------- launch -----------------------------------------------------
extern "C" void kernel_launch(void* const* d_in, const int* in_sizes, int n_in,
                              void* d_out, int out_size) {
    const float* inputs = (const float*)d_in[0];
    const float* Wx     = (const float*)d_in[1];
    const float* Wh     = (const float*)d_in[2];
    const float* b_rnn  = (const float*)d_in[3];
    const float* W1     = (const float*)d_in[4];
    const float* b1     = (const float*)d_in[5];
    const float* W2     = (const float*)d_in[6];
    const float* b2     = (const float*)d_in[7];

    float *xw, *h, *hid, *logits;
    cudaGetSymbolAddress((void**)&xw,     g_xw);
    cudaGetSymbolAddress((void**)&h,      g_hbuf);
    cudaGetSymbolAddress((void**)&hid,    g_hid);
    cudaGetSymbolAddress((void**)&logits, g_logits);

    // xw = inputs @ Wx + b_rnn  — 3xTF32 tensor-core GEMM
    const int ga_smem = 8 * GA_TILE * 4;
    cudaFuncSetAttribute(gemm_a_mma,
                         cudaFuncAttributeMaxDynamicSharedMemorySize, ga_smem);
    gemm_a_mma<<<dim3(H_ / 128, (B_ * T_) / 128), 256, ga_smem>>>(
        inputs, Wx, b_rnn, xw);

    // persistent recurrence + fused dense1 — 3xTF32 mma (R13 structure)
    const int smem = (int)sizeof(RecurSmem);   // 208896
    cudaFuncSetAttribute(rnn_recur, cudaFuncAttributeMaxDynamicSharedMemorySize, smem);
    rnn_recur<<<NBLK, RTHREADS, smem>>>(xw, Wh, W1, b1, h, hid);

    // logits = hid @ W2 + b2   (N=1000, ragged)
    sgemm_kernel<32, 64, 16, 4, 4, 128, false>
        <<<dim3((A_ + 63) / 64, B_ / 32), 128>>>(
            B_, A_, H_, hid, H_, W2, A_, b2, logits, A_);

    sample_kernel<<<B_, 256>>>();
    finalize_kernel<<<1, 256>>>((float*)d_out, out_size);
}

// round 17
// speedup vs baseline: 1.2758x; 1.0067x over previous
#include <cuda_runtime.h>
#include <cuda_bf16.h>
#include <cstdint>

#define B_ 256
#define T_ 256
#define F_ 512
#define H_ 1024
#define A_ 1000

// recurrence: 128 blocks = 2 row-groups(128) x 8 col-groups(128) x 8 k-splits(128)
#define NBLK 128
#define RTHREADS 512
#define RROWS 128
#define RCOLS 128
#define RK    128
#define NSPLIT 8
#define MPI   136   // smem pitch (floats): conflict-free mma fragment access

// ---------------- scratch (static device globals; no allocation) -------------
__device__ float g_xw[(size_t)B_ * T_ * H_];     // input projection [B][T][H]
__device__ float g_hbuf[B_ * H_];                // hidden state
__device__ float g_part[NSPLIT][B_ * H_];        // k-split partials [q][m][n]
__device__ float g_hid[B_ * H_];
__device__ float g_logits[B_ * A_];
__device__ int   g_action[B_];
__device__ float g_rowloss[B_];

// group barrier state: 2 independent 64-block barriers (row-group-local deps),
// padded to separate cache lines. Self-cleaning across graph replays.
__device__ unsigned g_cnt2[2 * 32] = {0};
__device__ volatile unsigned g_gen2[2 * 32];

// ---------------- packed fp32x2 FMA helpers (sgemm for logits) ---------------
__device__ __forceinline__ unsigned long long pack2(float lo, float hi) {
    unsigned long long r;
    asm("mov.b64 %0, {%1, %2};" : "=l"(r) : "f"(lo), "f"(hi));
    return r;
}
__device__ __forceinline__ void unpack2(unsigned long long v, float& lo, float& hi) {
    asm("mov.b64 {%0, %1}, %2;" : "=f"(lo), "=f"(hi) : "l"(v));
}
__device__ __forceinline__ void ffma2(unsigned long long& d, unsigned long long a,
                                      unsigned long long b) {
    asm("fma.rn.f32x2 %0, %1, %2, %0;" : "+l"(d) : "l"(a), "l"(b));
}

// ---------------- tf32 split + mma.sync helpers ------------------------------
__device__ __forceinline__ void tf32_split(float x, uint32_t& u0, uint32_t& u1) {
    asm("cvt.rna.tf32.f32 %0, %1;" : "=r"(u0) : "f"(x));
    float r = x - __uint_as_float(u0);
    asm("cvt.rna.tf32.f32 %0, %1;" : "=r"(u1) : "f"(r));
}
__device__ __forceinline__ void mma_tf32(float c[4], const uint32_t a[4],
                                         const uint32_t b[2]) {
    asm volatile(
        "mma.sync.aligned.m16n8k8.row.col.f32.tf32.tf32.f32 "
        "{%0,%1,%2,%3}, {%4,%5,%6,%7}, {%8,%9}, {%0,%1,%2,%3};"
        : "+f"(c[0]), "+f"(c[1]), "+f"(c[2]), "+f"(c[3])
        : "r"(a[0]), "r"(a[1]), "r"(a[2]), "r"(a[3]), "r"(b[0]), "r"(b[1]));
}

// ---------------- phase-A 3xTF32 tensor GEMM ---------------------------------
// xw[65536,1024] = inputs[65536,512] @ Wx[512,1024] + b_rnn
// CTA tile 128x128, 8 warps (2x4), warp tile 64x32, K-chunks of 16, dbl-buffered.
// Term-major MMA issue: same-accumulator MMAs are 4 apart (latency cover).
#define PITA 136
#define GA_CH 16
#define GA_NCH (F_ / GA_CH)        // 32 chunks
#define GA_TILE (GA_CH * PITA)

__global__ void __launch_bounds__(256, 1)
gemm_a_mma(const float* __restrict__ Ag, const float* __restrict__ Bg,
           const float* __restrict__ bias, float* __restrict__ C)
{
    extern __shared__ __align__(16) float sm[];
    float* sA0 = sm;
    float* sA1 = sm + 2 * GA_TILE;
    float* sB0 = sm + 4 * GA_TILE;
    float* sB1 = sm + 6 * GA_TILE;

    const int tid  = threadIdx.x;
    const int lane = tid & 31;
    const int w    = tid >> 5;
    const int wm   = w >> 2;
    const int wn   = w & 3;
    const int bm   = blockIdx.y * 128;
    const int bn   = blockIdx.x * 128;
    const int g    = lane >> 2;
    const int tg   = lane & 3;

    const int a_k4  = tid >> 7;
    const int a_row = tid & 127;
    const int b_k   = tid >> 5;
    const int b_n4  = lane;

    float4 aReg[2], bReg[2];
    auto loadG = [&](int k0) {
#pragma unroll
        for (int j = 0; j < 2; ++j) {
            aReg[j] = __ldg((const float4*)(Ag + (size_t)(bm + a_row) * F_ +
                                            k0 + (a_k4 + 2 * j) * 4));
            bReg[j] = __ldg((const float4*)(Bg + (size_t)(k0 + b_k + 8 * j) * H_ +
                                            bn + b_n4 * 4));
        }
    };
    auto storeS = [&](int buf) {
        float* dA0 = sA0 + buf * GA_TILE;
        float* dA1 = sA1 + buf * GA_TILE;
        float* dB0 = sB0 + buf * GA_TILE;
        float* dB1 = sB1 + buf * GA_TILE;
#pragma unroll
        for (int j = 0; j < 2; ++j) {
            const int kb = (a_k4 + 2 * j) * 4;
            const float av[4] = {aReg[j].x, aReg[j].y, aReg[j].z, aReg[j].w};
#pragma unroll
            for (int e = 0; e < 4; ++e) {
                uint32_t u0, u1;
                tf32_split(av[e], u0, u1);
                dA0[(kb + e) * PITA + a_row] = __uint_as_float(u0);
                dA1[(kb + e) * PITA + a_row] = __uint_as_float(u1);
            }
            const int kr = b_k + 8 * j;
            const float bv[4] = {bReg[j].x, bReg[j].y, bReg[j].z, bReg[j].w};
            uint4 q0, q1;
            uint32_t* p0 = (uint32_t*)&q0;
            uint32_t* p1 = (uint32_t*)&q1;
#pragma unroll
            for (int e = 0; e < 4; ++e) tf32_split(bv[e], p0[e], p1[e]);
            *(uint4*)(dB0 + kr * PITA + b_n4 * 4) = q0;
            *(uint4*)(dB1 + kr * PITA + b_n4 * 4) = q1;
        }
    };

    float c[4][4][4];
#pragma unroll
    for (int i = 0; i < 4; ++i)
#pragma unroll
        for (int j = 0; j < 4; ++j)
#pragma unroll
            for (int e = 0; e < 4; ++e) c[i][j][e] = 0.0f;

    loadG(0);
    storeS(0);
    __syncthreads();

    for (int kt = 0; kt < GA_NCH; ++kt) {
        const int cur = kt & 1;
        if (kt + 1 < GA_NCH) loadG((kt + 1) * GA_CH);

        const float* cA0 = sA0 + cur * GA_TILE;
        const float* cA1 = sA1 + cur * GA_TILE;
        const float* cB0 = sB0 + cur * GA_TILE;
        const float* cB1 = sB1 + cur * GA_TILE;

#pragma unroll
        for (int s = 0; s < 2; ++s) {
            const int ko = s * 8;
            uint32_t bt0[4][2], bt1[4][2];
#pragma unroll
            for (int in = 0; in < 4; ++in) {
                const int an = wn * 32 + in * 8 + g;
                bt0[in][0] = __float_as_uint(cB0[(ko + tg) * PITA + an]);
                bt0[in][1] = __float_as_uint(cB0[(ko + tg + 4) * PITA + an]);
                bt1[in][0] = __float_as_uint(cB1[(ko + tg) * PITA + an]);
                bt1[in][1] = __float_as_uint(cB1[(ko + tg + 4) * PITA + an]);
            }
#pragma unroll
            for (int im = 0; im < 4; ++im) {
                const int am = wm * 64 + im * 16 + g;
                uint32_t a0[4], a1[4];
                a0[0] = __float_as_uint(cA0[(ko + tg) * PITA + am]);
                a0[1] = __float_as_uint(cA0[(ko + tg) * PITA + am + 8]);
                a0[2] = __float_as_uint(cA0[(ko + tg + 4) * PITA + am]);
                a0[3] = __float_as_uint(cA0[(ko + tg + 4) * PITA + am + 8]);
                a1[0] = __float_as_uint(cA1[(ko + tg) * PITA + am]);
                a1[1] = __float_as_uint(cA1[(ko + tg) * PITA + am + 8]);
                a1[2] = __float_as_uint(cA1[(ko + tg + 4) * PITA + am]);
                a1[3] = __float_as_uint(cA1[(ko + tg + 4) * PITA + am + 8]);
                // term-major issue: same-accumulator MMAs 4 apart, order
                // per accumulator preserved (t1,t2,t3) -> bit-identical
#pragma unroll
                for (int in = 0; in < 4; ++in) mma_tf32(c[im][in], a0, bt1[in]);
#pragma unroll
                for (int in = 0; in < 4; ++in) mma_tf32(c[im][in], a1, bt0[in]);
#pragma unroll
                for (int in = 0; in < 4; ++in) mma_tf32(c[im][in], a0, bt0[in]);
            }
        }

        if (kt + 1 < GA_NCH) storeS(cur ^ 1);
        __syncthreads();
    }

#pragma unroll
    for (int im = 0; im < 4; ++im) {
        const int r0 = bm + wm * 64 + im * 16 + g;
#pragma unroll
        for (int in = 0; in < 4; ++in) {
            const int n0 = bn + wn * 32 + in * 8 + 2 * tg;
            float2 bv = *(const float2*)&bias[n0];
            float2 o0 = {c[im][in][0] + bv.x, c[im][in][1] + bv.y};
            float2 o1 = {c[im][in][2] + bv.x, c[im][in][3] + bv.y};
            *(float2*)&C[(size_t)r0 * H_ + n0]       = o0;
            *(float2*)&C[(size_t)(r0 + 8) * H_ + n0] = o1;
        }
    }
}

// ---------------- 64-block group barrier --------------------------------------
// The recurrence dataflow is row-group-local: block (r,c,q) only touches h
// rows / partial rows of its own r. Two independent barriers (64 arrivals)
// halve the straggler-max population vs one 128-block barrier.
__device__ __forceinline__ void group_sync(int grp) {
    __syncthreads();
    if (threadIdx.x == 0) {
        __threadfence();
        const int idx = grp * 32;
        unsigned gen = g_gen2[idx];
        unsigned old = atomicAdd(&g_cnt2[idx], 1u);
        if (old == (NBLK / 2) - 1) {
            g_cnt2[idx] = 0;
            __threadfence();
            g_gen2[idx] = gen + 1;
        } else {
            while (g_gen2[idx] == gen) { }
            __threadfence();
        }
    }
    __syncthreads();
}

// ---------------- persistent recurrence kernel: 3xTF32 mma -------------------
// (R13/R16 structure: h materialized, 2 group barriers/step, separate reduce,
//  512 threads, 16 warps 4x4, 4 chunks of 32 k, term-major MMA issue.)

struct RecurSmem {
    float W0[RK * MPI];          // 69632 B
    float W1s[RK * MPI];         // 69632 B
    float A0[2 * 32 * MPI];      // 34816 B (2 staging buffers, term 0)
    float A1[2 * 32 * MPI];      // 34816 B (term 1)
};                               // total 208896 B

__device__ __forceinline__ void split_slab(
    const float* __restrict__ Wg, float* __restrict__ sW0,
    float* __restrict__ sW1, int bk, int bn, int tid)
{
    for (int v = tid; v < RK * RCOLS / 4; v += RTHREADS) {
        int k = v >> 5, n4 = (v & 31) * 4;
        float4 wv = __ldg((const float4*)&Wg[(long)(bk + k) * H_ + bn + n4]);
        const float we[4] = {wv.x, wv.y, wv.z, wv.w};
#pragma unroll
        for (int e = 0; e < 4; ++e) {
            uint32_t u0, u1;
            tf32_split(we[e], u0, u1);
            sW0[k * MPI + n4 + e] = __uint_as_float(u0);
            sW1[k * MPI + n4 + e] = __uint_as_float(u1);
        }
    }
}

__device__ __forceinline__ void stage_chunk(
    float* __restrict__ sA0, float* __restrict__ sA1, int buf,
    int kq, int mcol, const float4 va[2])
{
    float* d0 = sA0 + buf * (32 * MPI);
    float* d1 = sA1 + buf * (32 * MPI);
#pragma unroll
    for (int j = 0; j < 2; ++j) {
        const float v[4] = {va[j].x, va[j].y, va[j].z, va[j].w};
#pragma unroll
        for (int e = 0; e < 4; ++e) {
            uint32_t u0, u1;
            tf32_split(v[e], u0, u1);
            const int kl = kq + j * 4 + e;
            d0[kl * MPI + mcol] = __uint_as_float(u0);
            d1[kl * MPI + mcol] = __uint_as_float(u1);
        }
    }
}

// full 128x128x128 tile GEMM: h (global) x resident slab -> c fragments
__device__ __forceinline__ void mma_tile(
    const float* __restrict__ hrow,            // &h[(bm+m_s)*H_ + bk + kq]
    const float* __restrict__ sW0, const float* __restrict__ sW1,
    float* __restrict__ sA0, float* __restrict__ sA1,
    int wr, int wc, int g, int tg, int mcol, int kq,
    float c[2][4][4])
{
    float4 va[2];
    va[0] = __ldcg((const float4*)(hrow));
    va[1] = __ldcg((const float4*)(hrow + 4));
    stage_chunk(sA0, sA1, 0, kq, mcol, va);
    __syncthreads();

    for (int ch = 0; ch < 4; ++ch) {
        const int buf = ch & 1;
        if (ch < 3) {
            va[0] = __ldcg((const float4*)(hrow + (ch + 1) * 32));
            va[1] = __ldcg((const float4*)(hrow + (ch + 1) * 32 + 4));
        }

        const float* cA0 = sA0 + buf * (32 * MPI);
        const float* cA1 = sA1 + buf * (32 * MPI);
#pragma unroll
        for (int ks = 0; ks < 4; ++ks) {
            const int kb = ch * 32 + ks * 8;   // slab (B) k
            const int ka = ks * 8;             // staging (A) k
            const int msw = ks << 3;
            uint32_t bt0[4][2], bt1[4][2];
#pragma unroll
            for (int in = 0; in < 4; ++in) {
                const int an = wc * 32 + in * 8 + g;
                bt0[in][0] = __float_as_uint(sW0[(kb + tg) * MPI + an]);
                bt0[in][1] = __float_as_uint(sW0[(kb + tg + 4) * MPI + an]);
                bt1[in][0] = __float_as_uint(sW1[(kb + tg) * MPI + an]);
                bt1[in][1] = __float_as_uint(sW1[(kb + tg + 4) * MPI + an]);
            }
#pragma unroll
            for (int im = 0; im < 2; ++im) {
                const int am  = (wr * 32 + im * 16 + g) ^ msw;
                const int am8 = (wr * 32 + im * 16 + g + 8) ^ msw;
                uint32_t a0[4], a1[4];
                a0[0] = __float_as_uint(cA0[(ka + tg) * MPI + am]);
                a0[1] = __float_as_uint(cA0[(ka + tg) * MPI + am8]);
                a0[2] = __float_as_uint(cA0[(ka + tg + 4) * MPI + am]);
                a0[3] = __float_as_uint(cA0[(ka + tg + 4) * MPI + am8]);
                a1[0] = __float_as_uint(cA1[(ka + tg) * MPI + am]);
                a1[1] = __float_as_uint(cA1[(ka + tg) * MPI + am8]);
                a1[2] = __float_as_uint(cA1[(ka + tg + 4) * MPI + am]);
                a1[3] = __float_as_uint(cA1[(ka + tg + 4) * MPI + am8]);
                // term-major issue: same-accumulator MMAs 4 apart, per-
                // accumulator term order preserved -> bit-identical result
#pragma unroll
                for (int in = 0; in < 4; ++in) mma_tf32(c[im][in], a0, bt1[in]);
#pragma unroll
                for (int in = 0; in < 4; ++in) mma_tf32(c[im][in], a1, bt0[in]);
#pragma unroll
                for (int in = 0; in < 4; ++in) mma_tf32(c[im][in], a0, bt0[in]);
            }
        }

        if (ch < 3) stage_chunk(sA0, sA1, buf ^ 1, kq, mcol, va);
        __syncthreads();
    }
}

__device__ __forceinline__ void store_partials(
    float c[2][4][4], float* __restrict__ pq,
    int bm, int bn, int wr, int wc, int g, int tg)
{
#pragma unroll
    for (int im = 0; im < 2; ++im) {
        const int r0 = bm + wr * 32 + im * 16 + g;
#pragma unroll
        for (int in = 0; in < 4; ++in) {
            const int n0 = bn + wc * 32 + in * 8 + 2 * tg;
            __stcg((float2*)&pq[(long)r0 * H_ + n0],
                   make_float2(c[im][in][0], c[im][in][1]));
            __stcg((float2*)&pq[(long)(r0 + 8) * H_ + n0],
                   make_float2(c[im][in][2], c[im][in][3]));
        }
    }
}

__global__ void __launch_bounds__(RTHREADS, 1)
rnn_recur(const float* __restrict__ xw, const float* __restrict__ Wh,
          const float* __restrict__ W1, const float* __restrict__ b1,
          float* __restrict__ h, float* __restrict__ hid)
{
    extern __shared__ __align__(16) char smraw[];
    RecurSmem* sm = (RecurSmem*)smraw;

    const int tid = threadIdx.x;
    const int bid = blockIdx.x;
    const int q = bid & 7;
    const int c_ = (bid >> 3) & 7;
    const int r = bid >> 6;
    const int bm = r * RROWS, bn = c_ * RCOLS, bk = q * RK;
    const int grp = r;                          // barrier group (row-group)

    const int w  = tid >> 5;
    const int wr = w >> 2, wc = w & 3;
    const int lane = tid & 31;
    const int g  = lane >> 2;
    const int tg = lane & 3;

    // staging mapping
    const int m_s = tid >> 2;          // 0..127
    const int kq  = (tid & 3) * 8;     // {0,8,16,24}
    const int mcol = m_s ^ ((tid & 3) << 3);   // XOR swizzle, (tid&3) == kl>>3

    const int gtid = bid * RTHREADS + tid;
    const int rm = gtid >> 8;
    const int rn4 = (gtid & 255) * 4;
    const long roff = (long)rm * H_ + rn4;

    // pre-split Wh slab (resident for all 255 steps)
    split_slab(Wh, sm->W0, sm->W1s, bk, bn, tid);

    // h_1 = relu(xw[:,0,:])
    {
        float4 v = __ldg((const float4*)&xw[((long)rm * T_ + 0) * H_ + rn4]);
        v.x = fmaxf(v.x, 0.f); v.y = fmaxf(v.y, 0.f);
        v.z = fmaxf(v.z, 0.f); v.w = fmaxf(v.w, 0.f);
        __stcg((float4*)&h[roff], v);
    }
    group_sync(grp);

    for (int t = 1; t < T_; ++t) {
        float4 xv = __ldcg((const float4*)&xw[((long)rm * T_ + t) * H_ + rn4]);

        float cf[2][4][4];
#pragma unroll
        for (int i = 0; i < 2; ++i)
#pragma unroll
            for (int j = 0; j < 4; ++j)
#pragma unroll
                for (int e = 0; e < 4; ++e) cf[i][j][e] = 0.0f;

        mma_tile(&h[(long)(bm + m_s) * H_ + bk + kq], sm->W0, sm->W1s,
                 sm->A0, sm->A1, wr, wc, g, tg, mcol, kq, cf);
        store_partials(cf, g_part[q], bm, bn, wr, wc, g, tg);
        group_sync(grp);

        // reduce: h = relu(xw[:,t,:] + sum_q partial_q)
        {
            float4 s = xv;
#pragma unroll
            for (int qq = 0; qq < NSPLIT; ++qq) {
                float4 p = __ldcg((const float4*)&g_part[qq][roff]);
                s.x += p.x; s.y += p.y; s.z += p.z; s.w += p.w;
            }
            s.x = fmaxf(s.x, 0.f); s.y = fmaxf(s.y, 0.f);
            s.z = fmaxf(s.z, 0.f); s.w = fmaxf(s.w, 0.f);
            __stcg((float4*)&h[roff], s);
        }
        group_sync(grp);
    }
    // h now holds h_last (h_256)

    // fused dense1: hid = relu(h_last @ W1 + b1) — re-split slab from W1
    split_slab(W1, sm->W0, sm->W1s, bk, bn, tid);
    __syncthreads();
    {
        float cf[2][4][4];
#pragma unroll
        for (int i = 0; i < 2; ++i)
#pragma unroll
            for (int j = 0; j < 4; ++j)
#pragma unroll
                for (int e = 0; e < 4; ++e) cf[i][j][e] = 0.0f;
        mma_tile(&h[(long)(bm + m_s) * H_ + bk + kq], sm->W0, sm->W1s,
                 sm->A0, sm->A1, wr, wc, g, tg, mcol, kq, cf);
        store_partials(cf, g_part[q], bm, bn, wr, wc, g, tg);
        group_sync(grp);
        {
            float4 s = __ldg((const float4*)&b1[rn4]);
#pragma unroll
            for (int qq = 0; qq < NSPLIT; ++qq) {
                float4 p = __ldcg((const float4*)&g_part[qq][roff]);
                s.x += p.x; s.y += p.y; s.z += p.z; s.w += p.w;
            }
            s.x = fmaxf(s.x, 0.f); s.y = fmaxf(s.y, 0.f);
            s.z = fmaxf(s.z, 0.f); s.w = fmaxf(s.w, 0.f);
            __stcg((float4*)&hid[roff], s);
        }
    }
}

// ---------------- double-buffered SGEMM (dup-A; logits) ----------------------
template <int BM, int BN, int BK, int TM, int TN, int THREADS, bool RELU>
__global__ void __launch_bounds__(THREADS)
sgemm_kernel(int M, int N, int K,
             const float* __restrict__ A, int lda,
             const float* __restrict__ Bm, int ldb,
             const float* __restrict__ bias,
             float* __restrict__ C, int ldc)
{
    static_assert(TN % 4 == 0 && TM % 2 == 0, "");
    constexpr int TX = BN / TN;
    constexpr int TY = BM / TM;
    static_assert(TX * TY == THREADS, "");

    __shared__ __align__(16) unsigned long long As[2][BK][BM];
    __shared__ __align__(16) float Bs[2][BK][BN];

    const int tid = threadIdx.x;
    const int tx  = tid % TX;
    const int ty  = tid / TX;
    const int bm  = blockIdx.y * BM;
    const int bn  = blockIdx.x * BN;

    constexpr int A_VECS = BM * BK / 4;
    constexpr int A_PER  = A_VECS / THREADS;
    constexpr int B_VECS = BK * BN / 4;
    constexpr int B_PER  = B_VECS / THREADS;
    static_assert(A_VECS % THREADS == 0 && B_VECS % THREADS == 0, "");

    float4 aReg[A_PER];
    float4 bReg[B_PER];

    auto loadA = [&](int k0) {
#pragma unroll
        for (int i = 0; i < A_PER; ++i) {
            int v   = tid + i * THREADS;
            int row = v / (BK / 4);
            int kc  = (v % (BK / 4)) * 4;
            aReg[i] = *reinterpret_cast<const float4*>(
                &A[(long)(bm + row) * lda + k0 + kc]);
        }
    };
    auto loadB = [&](int k0) {
#pragma unroll
        for (int i = 0; i < B_PER; ++i) {
            int v    = tid + i * THREADS;
            int krow = v / (BN / 4);
            int nc   = (v % (BN / 4)) * 4;
            int col  = bn + nc;
            if (col < N)
                bReg[i] = *reinterpret_cast<const float4*>(
                    &Bm[(long)(k0 + krow) * ldb + col]);
            else
                bReg[i] = make_float4(0.f, 0.f, 0.f, 0.f);
        }
    };
    auto storeA = [&](int buf) {
#pragma unroll
        for (int i = 0; i < A_PER; ++i) {
            int v   = tid + i * THREADS;
            int row = v / (BK / 4);
            int kc  = (v % (BK / 4)) * 4;
            As[buf][kc + 0][row] = pack2(aReg[i].x, aReg[i].x);
            As[buf][kc + 1][row] = pack2(aReg[i].y, aReg[i].y);
            As[buf][kc + 2][row] = pack2(aReg[i].z, aReg[i].z);
            As[buf][kc + 3][row] = pack2(aReg[i].w, aReg[i].w);
        }
    };
    auto storeB = [&](int buf) {
#pragma unroll
        for (int i = 0; i < B_PER; ++i) {
            int v    = tid + i * THREADS;
            int krow = v / (BN / 4);
            int nc   = (v % (BN / 4)) * 4;
            *reinterpret_cast<float4*>(&Bs[buf][krow][nc]) = bReg[i];
        }
    };

    unsigned long long acc[TM][TN / 2];
#pragma unroll
    for (int i = 0; i < TM; ++i)
#pragma unroll
        for (int j = 0; j < TN / 2; ++j) acc[i][j] = 0ull;

    loadA(0); loadB(0);
    storeA(0); storeB(0);
    __syncthreads();

    const int nTiles = K / BK;
    for (int kt = 0; kt < nTiles; ++kt) {
        const int cur = kt & 1, nxt = cur ^ 1;
        if (kt + 1 < nTiles) { loadA((kt + 1) * BK); loadB((kt + 1) * BK); }

#pragma unroll
        for (int kk = 0; kk < BK; ++kk) {
            unsigned long long a2[TM];
#pragma unroll
            for (int i = 0; i < TM; i += 2) {
                ulonglong2 t = *reinterpret_cast<const ulonglong2*>(
                    &As[cur][kk][ty * TM + i]);
                a2[i] = t.x; a2[i + 1] = t.y;
            }
            unsigned long long b2[TN / 2];
#pragma unroll
            for (int j = 0; j < TN / 4; ++j) {
                ulonglong2 bv = *reinterpret_cast<const ulonglong2*>(
                    &Bs[cur][kk][tx * TN + 4 * j]);
                b2[2 * j] = bv.x; b2[2 * j + 1] = bv.y;
            }
#pragma unroll
            for (int i = 0; i < TM; ++i)
#pragma unroll
                for (int j = 0; j < TN / 2; ++j) ffma2(acc[i][j], a2[i], b2[j]);
        }

        if (kt + 1 < nTiles) { storeA(nxt); storeB(nxt); }
        __syncthreads();
    }

#pragma unroll
    for (int i = 0; i < TM; ++i) {
        const int m = bm + ty * TM + i;
#pragma unroll
        for (int j = 0; j < TN / 2; ++j) {
            float lo, hi;
            unpack2(acc[i][j], lo, hi);
            float v[2] = {lo, hi};
            const int n0 = bn + tx * TN + 2 * j;
#pragma unroll
            for (int e = 0; e < 2; ++e) {
                const int n = n0 + e;
                if (n < N) {
                    float cv = v[e];
                    if (bias) cv += bias[n];
                    if (RELU) cv = fmaxf(cv, 0.0f);
                    C[(long)m * ldc + n] = cv;
                }
            }
        }
    }
}

// ---------------- threefry2x32 / JAX gumbel ----------------------------------
__device__ __forceinline__ float gumbel_at(uint32_t idx) {
    const uint32_t k0 = 0u, k1 = 42u;
    const uint32_t ks2 = k0 ^ k1 ^ 0x1BD11BDAu;
    uint32_t x0 = k0;
    uint32_t x1 = idx + k1;
#define RND(r) { x0 += x1; x1 = ((x1 << (r)) | (x1 >> (32 - (r)))) ^ x0; }
    RND(13) RND(15) RND(26) RND(6)   x0 += k1;  x1 += ks2 + 1u;
    RND(17) RND(29) RND(16) RND(24)  x0 += ks2; x1 += k0 + 2u;
    RND(13) RND(15) RND(26) RND(6)   x0 += k0;  x1 += k1 + 3u;
    RND(17) RND(29) RND(16) RND(24)  x0 += k1;  x1 += ks2 + 4u;
    RND(13) RND(15) RND(26) RND(6)   x0 += ks2; x1 += k0 + 5u;
#undef RND
    const uint32_t bits = x0 ^ x1;
    float f = __uint_as_float((bits >> 9) | 0x3f800000u) - 1.0f;
    float u = fmaxf(f, 1.17549435e-38f);
    return -logf(-logf(u));
}

// ---------------- softmax+sample, finalize -----------------------------------
__global__ void sample_kernel() {
    const int b = blockIdx.x;
    const float* __restrict__ row = g_logits + (long)b * A_;
    const int tid = threadIdx.x;
    __shared__ float sred[256];
    __shared__ int   sidx[256];

    float mx = -3.402823466e38f;
    for (int a = tid; a < A_; a += 256) mx = fmaxf(mx, row[a]);
    sred[tid] = mx; __syncthreads();
    for (int s = 128; s; s >>= 1) {
        if (tid < s) sred[tid] = fmaxf(sred[tid], sred[tid + s]);
        __syncthreads();
    }
    const float rmax = sred[0]; __syncthreads();

    float sum = 0.f;
    for (int a = tid; a < A_; a += 256) sum += expf(row[a] - rmax);
    sred[tid] = sum; __syncthreads();
    for (int s = 128; s; s >>= 1) {
        if (tid < s) sred[tid] += sred[tid + s];
        __syncthreads();
    }
    const float rsum = sred[0]; __syncthreads();

    float bestv = -3.402823466e38f;
    int   besti = A_;
    for (int a = tid; a < A_; a += 256) {
        float p = expf(row[a] - rmax) / rsum;
        float v = p + gumbel_at((uint32_t)(b * A_ + a));
        if (v > bestv) { bestv = v; besti = a; }
    }
    sred[tid] = bestv; sidx[tid] = besti; __syncthreads();
    for (int s = 128; s; s >>= 1) {
        if (tid < s) {
            float v2 = sred[tid + s]; int i2 = sidx[tid + s];
            if (v2 > sred[tid] || (v2 == sred[tid] && i2 < sidx[tid])) {
                sred[tid] = v2; sidx[tid] = i2;
            }
        }
        __syncthreads();
    }
    if (tid == 0) {
        const int a = sidx[0];
        g_action[b] = a;
        float p = expf(row[a] - rmax) / rsum;
        p = fminf(fmaxf(p, 1e-7f), 1.0f - 1e-7f);
        g_rowloss[b] = -logf(p);
    }
}

__global__ void finalize_kernel(float* __restrict__ out, int out_size) {
    const int tid = threadIdx.x;
    __shared__ float red[256];
    red[tid] = g_rowloss[tid];
    __syncthreads();
    for (int s = 128; s; s >>= 1) {
        if (tid < s) red[tid] += red[tid + s];
        __syncthreads();
    }
    const float loss = red[0] / (float)B_;

    if (out_size == 1) {
        if (tid == 0) out[0] = loss;
        return;
    }
    if (tid < B_ && tid < out_size) out[tid] = (float)g_action[tid];
    if (tid == 0 && out_size > B_) out[B_] = loss;
    for (int i = B_ + 1 + tid; i < out_size; i += 256) out[i] = 0.0f;
}

// ---------------- launch -----------------------------------------------------
extern "C" void kernel_launch(void* const* d_in, const int* in_sizes, int n_in,
                              void* d_out, int out_size) {
    const float* inputs = (const float*)d_in[0];
    const float* Wx     = (const float*)d_in[1];
    const float* Wh     = (const float*)d_in[2];
    const float* b_rnn  = (const float*)d_in[3];
    const float* W1     = (const float*)d_in[4];
    const float* b1     = (const float*)d_in[5];
    const float* W2     = (const float*)d_in[6];
    const float* b2     = (const float*)d_in[7];

    float *xw, *h, *hid, *logits;
    cudaGetSymbolAddress((void**)&xw,     g_xw);
    cudaGetSymbolAddress((void**)&h,      g_hbuf);
    cudaGetSymbolAddress((void**)&hid,    g_hid);
    cudaGetSymbolAddress((void**)&logits, g_logits);

    // xw = inputs @ Wx + b_rnn  — 3xTF32 tensor-core GEMM
    const int ga_smem = 8 * GA_TILE * 4;
    cudaFuncSetAttribute(gemm_a_mma,
                         cudaFuncAttributeMaxDynamicSharedMemorySize, ga_smem);
    gemm_a_mma<<<dim3(H_ / 128, (B_ * T_) / 128), 256, ga_smem>>>(
        inputs, Wx, b_rnn, xw);

    // persistent recurrence + fused dense1 — 3xTF32 mma, group barriers
    const int smem = (int)sizeof(RecurSmem);   // 208896
    cudaFuncSetAttribute(rnn_recur, cudaFuncAttributeMaxDynamicSharedMemorySize, smem);
    rnn_recur<<<NBLK, RTHREADS, smem>>>(xw, Wh, W1, b1, h, hid);

    // logits = hid @ W2 + b2   (N=1000, ragged)
    sgemm_kernel<32, 64, 16, 4, 4, 128, false>
        <<<dim3((A_ + 63) / 64, B_ / 32), 128>>>(
            B_, A_, H_, hid, H_, W2, A_, b2, logits, A_);

    sample_kernel<<<B_, 256>>>();
    finalize_kernel<<<1, 256>>>((float*)d_out, out_size);
}